// round 11
// baseline (speedup 1.0000x reference)
#include <cuda_runtime.h>
#include <cuda_fp16.h>
#include <cstdint>

#define N_TOKENS   1000000
#define NFEAT      128
#define NCLUST     64
#define TILE_TOK   128
#define NUM_TILES  ((N_TOKENS + TILE_TOK - 1) / TILE_TOK)   // 7813
#define GRID_MAIN  148
#define GB_STRIDE  16
#define CAP        256                      // candidate entries per thread
#define NSLOTS     (GRID_MAIN * 256)
#define SCAP       4096                     // shortlist cap per cluster

// ---- smem layout (pass 1) ----
#define SM_RAW   0                          // 2 x 64KB fp32 staging
#define SM_XHI   131072                     // 128 x 256B fp16 tile
#define SM_CHI   (SM_XHI + 32768)           // 64 x 256B fp16 tile
#define SM_X2    (SM_CHI + 16384)           // 128 f32
#define SM_KC    (SM_X2 + 512)              // c2max (uint-mapped float)
#define SM_TOTAL (SM_KC + 16)               // 181264

// g_best[k*16]: max of ~((mapped(U)<<32)|0)  ->  min U per cluster
__device__ unsigned long long g_best[NCLUST * GB_STRIDE];
__device__ unsigned long long g_cand[(size_t)NSLOTS * CAP];   // (mapL<<32)|(cl<<20)|tok
__device__ unsigned int       g_cnt[NSLOTS];
__device__ unsigned int       g_short[NCLUST * SCAP];
__device__ unsigned int       g_shortcnt[NCLUST];
__device__ unsigned int       g_overflow;

__device__ __forceinline__ uint32_t smem_u32(const void* p) {
    uint32_t a;
    asm("{ .reg .u64 t; cvta.to.shared.u64 t, %1; cvt.u32.u64 %0, t; }" : "=r"(a) : "l"(p));
    return a;
}
__device__ __forceinline__ void cp_async16(uint32_t dst, const void* src) {
    asm volatile("cp.async.cg.shared.global [%0], [%1], 16;" :: "r"(dst), "l"(src));
}
#define CP_COMMIT() asm volatile("cp.async.commit_group;" ::: "memory")
#define CP_WAIT1()  asm volatile("cp.async.wait_group 1;" ::: "memory")
#define BAR_PAIR(id) asm volatile("bar.sync %0, 64;" :: "r"(id) : "memory")

__device__ __forceinline__ void ldsm4(uint32_t (&r)[4], uint32_t addr) {
    asm volatile("ldmatrix.sync.aligned.m8n8.x4.shared.b16 {%0,%1,%2,%3}, [%4];"
        : "=r"(r[0]), "=r"(r[1]), "=r"(r[2]), "=r"(r[3]) : "r"(addr));
}
__device__ __forceinline__ void mma16816(float (&d)[4], const uint32_t (&a)[4],
                                         uint32_t b0, uint32_t b1) {
    asm volatile("mma.sync.aligned.m16n8k16.row.col.f32.f16.f16.f32 "
        "{%0,%1,%2,%3}, {%4,%5,%6,%7}, {%8,%9}, {%0,%1,%2,%3};"
        : "+f"(d[0]), "+f"(d[1]), "+f"(d[2]), "+f"(d[3])
        : "r"(a[0]), "r"(a[1]), "r"(a[2]), "r"(a[3]), "r"(b0), "r"(b1));
}

// monotonic float->uint map (order preserved, incl. negatives)
__device__ __forceinline__ unsigned fmap(float f) {
    unsigned u = __float_as_uint(f);
    return (u & 0x80000000u) ? ~u : (u | 0x80000000u);
}
__device__ __forceinline__ uint32_t pack_h2(__half a, __half b) {
    return (uint32_t)__half_as_ushort(a) | ((uint32_t)__half_as_ushort(b) << 16);
}

__global__ void reset_kernel() {
    int i = threadIdx.x;
    if (i < NCLUST) { g_best[i * GB_STRIDE] = 0ull; g_shortcnt[i] = 0u; }
    if (i == 0) g_overflow = 0u;
}

__global__ __launch_bounds__(256, 1)
void cluster_main(const float* __restrict__ x, const float* __restrict__ cc) {
    extern __shared__ char smem[];
    const uint32_t sm = smem_u32(smem);
    const int tid  = threadIdx.x;
    const int wid  = tid >> 5;
    const int lane = tid & 31;

    const int strip = wid >> 1;
    const int tb    = strip * 32;
    const int cb    = (wid & 1) * 32;
    const int rbase = tb + (wid & 1) * 16;
    const int barid = strip + 1;

    float* x2s = (float*)(smem + SM_X2);
    unsigned* kcm = (unsigned*)(smem + SM_KC);
    if (tid == 0) *kcm = 0u;

    const float4* xg4 = (const float4*)x;

    int ntiles = 0;
    for (int t = blockIdx.x; t < NUM_TILES; t += GRID_MAIN) ++ntiles;

    auto issue_rows = [&](int tile_idx, int buf) {
        const int tokBase = tile_idx * TILE_TOK;
        const uint32_t base = sm + SM_RAW + (uint32_t)buf * 65536;
        #pragma unroll
        for (int i = 0; i < 16; ++i) {
            int f   = lane + i * 32;
            int tl  = rbase + (f >> 5);
            int dq  = f & 31;
            int gtok = tokBase + tl;
            if (gtok >= N_TOKENS) gtok = N_TOKENS - 1;
            uint32_t dst = base + (uint32_t)tl * 512
                         + (uint32_t)((dq ^ (((tl & 3) << 1) | (dq >> 4))) * 16);
            cp_async16(dst, xg4 + (size_t)gtok * 32 + dq);
        }
    };

    int tile = blockIdx.x;
    if (ntiles > 0) issue_rows(tile, 0);
    CP_COMMIT();
    __syncthreads();                        // kcm zero visible

    // ---- centers: convert hi tile + per-cluster |c|^2 max ----
    if (tid < 128) {
        int rr = tid >> 1, hh = tid & 1;
        const float* cg = cc + rr * NFEAT + hh * 64;
        float c2h = 0.f;
        #pragma unroll
        for (int c = 0; c < 8; ++c) {
            __half hv[8];
            #pragma unroll
            for (int t = 0; t < 8; ++t) {
                float v = cg[c * 8 + t];
                c2h = fmaf(v, v, c2h);
                hv[t] = __float2half_rn(v);
            }
            uint4 vh;
            vh.x = pack_h2(hv[0], hv[1]); vh.y = pack_h2(hv[2], hv[3]);
            vh.z = pack_h2(hv[4], hv[5]); vh.w = pack_h2(hv[6], hv[7]);
            uint32_t phys = (uint32_t)(((hh * 8 + c) ^ (rr & 7)) * 16) + (uint32_t)rr * 256;
            *(uint4*)(smem + SM_CHI + phys) = vh;
        }
        float c2 = c2h + __shfl_xor_sync(0xffffffffu, c2h, 1);
        if (hh == 0) atomicMax(kcm, __float_as_uint(c2));   // c2 > 0
    }
    __syncthreads();
    // K = 1.25 * 2^-9 * Cmax ; E = K*|x| + 1e-4
    const float kconst = 1.25f * 0.001953125f * sqrtf(__uint_as_float(*kcm));

    // ---- ldmatrix lane addressing ----
    const int rowA  = tb + (lane & 15);
    const int khA   = lane >> 4;
    const int nrowB = cb + (lane & 7) + ((lane >> 4) & 1) * 8;
    const int khB   = (lane >> 3) & 1;

    // cluster index per accumulator column j
    int clj[8];
    #pragma unroll
    for (int j = 0; j < 8; ++j)
        clj[j] = cb + (j >> 1) * 8 + 2 * (lane & 3) + (j & 1);

    float rminU[8];
    #pragma unroll
    for (int j = 0; j < 8; ++j) rminU[j] = __int_as_float(0x7f800000);

    const uint32_t slot = (uint32_t)blockIdx.x * 256 + tid;
    unsigned long long* cbuf = g_cand + (size_t)slot * CAP;
    unsigned cnt = 0;

    const int crow = rbase + (lane >> 1);
    const int chal = lane & 1;

    for (int it = 0; it < ntiles; ++it, tile += GRID_MAIN) {
        const int tokBase = tile * TILE_TOK;
        const int buf = it & 1;

        if (it + 1 < ntiles) issue_rows(tile + GRID_MAIN, buf ^ 1);
        CP_COMMIT();
        CP_WAIT1();

        // ---- convert own 16 rows -> XHI (hi only); fused exact x^2 ----
        {
            const char* raw = smem + SM_RAW + (size_t)buf * 65536 + (size_t)crow * 512;
            const int xorv = ((crow & 3) << 1) | chal;
            float ss = 0.f;
            #pragma unroll
            for (int c = 0; c < 8; ++c) {
                int a0 = chal * 16 + 2 * c;
                float e[8];
                *(float4*)(e)     = *(const float4*)(raw + ((a0       ^ xorv) * 16));
                *(float4*)(e + 4) = *(const float4*)(raw + (((a0 + 1) ^ xorv) * 16));
                __half hv[8];
                #pragma unroll
                for (int t = 0; t < 8; ++t) {
                    float v = e[t];
                    ss = fmaf(v, v, ss);
                    hv[t] = __float2half_rn(v);
                }
                uint4 vh;
                vh.x = pack_h2(hv[0], hv[1]); vh.y = pack_h2(hv[2], hv[3]);
                vh.z = pack_h2(hv[4], hv[5]); vh.w = pack_h2(hv[6], hv[7]);
                uint32_t phys = (uint32_t)crow * 256
                              + (uint32_t)(((chal * 8 + c) ^ (crow & 7)) * 16);
                *(uint4*)(smem + SM_XHI + phys) = vh;
            }
            float tot = ss + __shfl_xor_sync(0xffffffffu, ss, 1);
            if (chal == 0) x2s[crow] = tot;
        }
        BAR_PAIR(barid);

        // ---- single-term hi*hi MMA: 8 k-steps ----
        float d[2][4][4];
        #pragma unroll
        for (int mt = 0; mt < 2; ++mt)
            #pragma unroll
            for (int nt = 0; nt < 4; ++nt)
                #pragma unroll
                for (int i = 0; i < 4; ++i) d[mt][nt][i] = 0.f;

        const uint32_t abase = sm + SM_XHI;
        const uint32_t bbase = sm + SM_CHI;
        #pragma unroll
        for (int k = 0; k < 8; ++k) {
            uint32_t aF[2][4], bF[2][4];
            const int ca  = 2 * k + khA;
            const int cbk = 2 * k + khB;
            #pragma unroll
            for (int mt = 0; mt < 2; ++mt) {
                int r = rowA + mt * 16;
                ldsm4(aF[mt], abase + (uint32_t)(r * 256 + ((ca ^ (r & 7)) * 16)));
            }
            #pragma unroll
            for (int np = 0; np < 2; ++np) {
                int r = nrowB + np * 16;
                ldsm4(bF[np], bbase + (uint32_t)(r * 256 + ((cbk ^ (r & 7)) * 16)));
            }
            #pragma unroll
            for (int mt = 0; mt < 2; ++mt) {
                mma16816(d[mt][0], aF[mt], bF[0][0], bF[0][1]);
                mma16816(d[mt][1], aF[mt], bF[0][2], bF[0][3]);
                mma16816(d[mt][2], aF[mt], bF[1][0], bF[1][1]);
                mma16816(d[mt][3], aF[mt], bF[1][2], bF[1][3]);
            }
        }

        // ---- epilogue: interval argmin candidate collection ----
        #pragma unroll
        for (int mt = 0; mt < 2; ++mt) {
            #pragma unroll
            for (int h = 0; h < 2; ++h) {
                const int tloc = tb + mt * 16 + (lane >> 2) + h * 8;
                const int gtok = tokBase + tloc;
                if (gtok < N_TOKENS) {
                    const float xv = x2s[tloc];
                    const float E  = fmaf(kconst, sqrtf(xv), 1e-4f);
                    #pragma unroll
                    for (int nt = 0; nt < 4; ++nt) {
                        #pragma unroll
                        for (int p = 0; p < 2; ++p) {
                            const int j = nt * 2 + p;
                            float s = fmaf(-2.f, d[mt][nt][h * 2 + p], xv);
                            float U = s + E;
                            float L = s - E;
                            if (U < rminU[j]) rminU[j] = U;
                            if (L <= rminU[j]) {
                                if (cnt < CAP)
                                    cbuf[cnt] = ((unsigned long long)fmap(L) << 32)
                                              | ((unsigned long long)clj[j] << 20)
                                              | (unsigned)gtok;
                                ++cnt;
                            }
                        }
                    }
                }
            }
        }
        BAR_PAIR(barid);
    }

    // ---- finalize: counts + global min-U per cluster ----
    g_cnt[slot] = (cnt > CAP) ? CAP : cnt;
    if (cnt > CAP) g_overflow = 1u;

    #pragma unroll
    for (int j = 0; j < 8; ++j) {
        float v = rminU[j];
        #pragma unroll
        for (int off = 4; off < 32; off <<= 1)
            v = fminf(v, __shfl_xor_sync(0xffffffffu, v, off));
        if ((lane >> 2) == 0) {
            unsigned long long key = ~(((unsigned long long)fmap(v) << 32));
            atomicMax(&g_best[clj[j] * GB_STRIDE], key);
        }
    }
}

// pass 2a: filter candidates against global min-U, bucket by cluster
__global__ void filter_kernel() {
    const uint32_t slot = (uint32_t)blockIdx.x * 256 + threadIdx.x;
    const unsigned n = g_cnt[slot];
    const unsigned long long* cbuf = g_cand + (size_t)slot * CAP;
    for (unsigned i = 0; i < n; ++i) {
        unsigned long long e = cbuf[i];
        unsigned mapL = (unsigned)(e >> 32);
        unsigned cl   = (unsigned)(e >> 20) & 63u;
        unsigned tok  = (unsigned)(e & 0xFFFFFu);
        unsigned gU   = (unsigned)((~g_best[cl * GB_STRIDE]) >> 32);
        if (mapL <= gU) {
            unsigned pos = atomicAdd(&g_shortcnt[cl], 1u);
            if (pos < SCAP) g_short[cl * SCAP + pos] = tok;
            else g_overflow = 1u;
        }
    }
}

// pass 2b: exact (double) rescore of shortlist, emit winner row
__global__ void gather_rescore(const float* __restrict__ x,
                               const float* __restrict__ cc,
                               float* __restrict__ out) {
    __shared__ float ck[NFEAT];
    __shared__ double sd[256];
    __shared__ unsigned st[256];
    const int k = blockIdx.x;
    const int tid = threadIdx.x;
    if (tid < NFEAT) ck[tid] = cc[k * NFEAT + tid];
    __syncthreads();

    double bd = 1.0e300;
    unsigned bt = 0xFFFFFFFFu;
    const unsigned ovf = g_overflow;
    unsigned n = g_shortcnt[k];
    if (n > SCAP) n = SCAP;

    if (ovf || n == 0) {
        // exact fallback: scan all tokens (never taken in practice)
        for (unsigned t = tid; t < N_TOKENS; t += 256) {
            double acc = 0.0;
            const float* xr = x + (size_t)t * NFEAT;
            for (int d = 0; d < NFEAT; ++d) {
                double df = (double)xr[d] - (double)ck[d];
                acc += df * df;
            }
            if (acc < bd || (acc == bd && t < bt)) { bd = acc; bt = t; }
        }
    } else {
        for (unsigned i = tid; i < n; i += 256) {
            unsigned t = g_short[k * SCAP + i];
            double acc = 0.0;
            const float* xr = x + (size_t)t * NFEAT;
            #pragma unroll 4
            for (int d = 0; d < NFEAT; ++d) {
                double df = (double)xr[d] - (double)ck[d];
                acc += df * df;
            }
            if (acc < bd || (acc == bd && t < bt)) { bd = acc; bt = t; }
        }
    }

    sd[tid] = bd; st[tid] = bt;
    __syncthreads();
    for (int s = 128; s > 0; s >>= 1) {
        if (tid < s) {
            if (sd[tid + s] < sd[tid] ||
                (sd[tid + s] == sd[tid] && st[tid + s] < st[tid])) {
                sd[tid] = sd[tid + s]; st[tid] = st[tid + s];
            }
        }
        __syncthreads();
    }
    unsigned w = st[0];
    if (tid < NFEAT) out[k * NFEAT + tid] = x[(size_t)w * NFEAT + tid];
}

extern "C" void kernel_launch(void* const* d_in, const int* in_sizes, int n_in,
                              void* d_out, int out_size) {
    const float* x;
    const float* cc;
    if (n_in >= 2 && in_sizes[0] == NCLUST * NFEAT) {
        cc = (const float*)d_in[0];
        x  = (const float*)d_in[1];
    } else {
        x  = (const float*)d_in[0];
        cc = (const float*)d_in[1];
    }
    float* out = (float*)d_out;

    cudaFuncSetAttribute(cluster_main,
                         cudaFuncAttributeMaxDynamicSharedMemorySize, SM_TOTAL);

    reset_kernel<<<1, 64>>>();
    cluster_main<<<GRID_MAIN, 256, SM_TOTAL>>>(x, cc);
    filter_kernel<<<GRID_MAIN, 256>>>();
    gather_rescore<<<NCLUST, 256>>>(x, cc, out);
}

// round 13
// speedup vs baseline: 1.3284x; 1.3284x over previous
#include <cuda_runtime.h>
#include <cuda_fp16.h>
#include <cstdint>

#define N_TOKENS   1000000
#define NFEAT      128
#define NCLUST     64
#define TILE_TOK   64
#define NUM_TILES  ((N_TOKENS + TILE_TOK - 1) / TILE_TOK)   // 15625
#define GRID_MAIN  296
#define GB_STRIDE  16
#define CAP        256
#define NSLOTS     (GRID_MAIN * 256)
#define SCAP       4096

// ---- smem layout ----
#define SM_RAW   0                           // 2 x 32KB fp32 staging
#define SM_XHI   65536                       // 64 x 256B fp16
#define SM_CHI   81920                       // 64 x 256B fp16
#define SM_X2E   98304                       // 64 x float2 (x2, E)
#define SM_KC    98816
#define SM_TOTAL 98832                       // x2 CTAs = 197664 < 228KB

__device__ unsigned long long g_best[NCLUST * GB_STRIDE];
__device__ unsigned long long g_cand[(size_t)NSLOTS * CAP];   // (mapL<<32)|(cl<<20)|tok
__device__ unsigned int       g_cnt[NSLOTS];
__device__ unsigned int       g_short[NCLUST * SCAP];
__device__ unsigned int       g_shortcnt[NCLUST];
__device__ unsigned int       g_overflow;

__device__ __forceinline__ uint32_t smem_u32(const void* p) {
    uint32_t a;
    asm("{ .reg .u64 t; cvta.to.shared.u64 t, %1; cvt.u32.u64 %0, t; }" : "=r"(a) : "l"(p));
    return a;
}
__device__ __forceinline__ void cp_async16(uint32_t dst, const void* src) {
    asm volatile("cp.async.cg.shared.global [%0], [%1], 16;" :: "r"(dst), "l"(src));
}
#define CP_COMMIT() asm volatile("cp.async.commit_group;" ::: "memory")
#define CP_WAIT1()  asm volatile("cp.async.wait_group 1;" ::: "memory")
#define BAR_PAIR(id) asm volatile("bar.sync %0, 64;" :: "r"(id) : "memory")

__device__ __forceinline__ void ldsm4(uint32_t (&r)[4], uint32_t addr) {
    asm volatile("ldmatrix.sync.aligned.m8n8.x4.shared.b16 {%0,%1,%2,%3}, [%4];"
        : "=r"(r[0]), "=r"(r[1]), "=r"(r[2]), "=r"(r[3]) : "r"(addr));
}
__device__ __forceinline__ void mma16816(float (&d)[4], const uint32_t (&a)[4],
                                         uint32_t b0, uint32_t b1) {
    asm volatile("mma.sync.aligned.m16n8k16.row.col.f32.f16.f16.f32 "
        "{%0,%1,%2,%3}, {%4,%5,%6,%7}, {%8,%9}, {%0,%1,%2,%3};"
        : "+f"(d[0]), "+f"(d[1]), "+f"(d[2]), "+f"(d[3])
        : "r"(a[0]), "r"(a[1]), "r"(a[2]), "r"(a[3]), "r"(b0), "r"(b1));
}
__device__ __forceinline__ unsigned fmap(float f) {
    unsigned u = __float_as_uint(f);
    return (u & 0x80000000u) ? ~u : (u | 0x80000000u);
}
__device__ __forceinline__ uint32_t pack_h2(__half a, __half b) {
    return (uint32_t)__half_as_ushort(a) | ((uint32_t)__half_as_ushort(b) << 16);
}
// raw-staging swizzle: bijective in dq per row; folds quarter bits + row bits into banks
__device__ __forceinline__ uint32_t raw_phys(int row, int dq) {
    uint32_t mask = (uint32_t)((((dq >> 3) & 3) ^ ((row >> 1) & 3)) | ((row & 1) << 2));
    return (uint32_t)(dq ^ (int)mask) * 16u;
}

__global__ void reset_kernel() {
    int i = threadIdx.x;
    if (i < NCLUST) { g_best[i * GB_STRIDE] = 0ull; g_shortcnt[i] = 0u; }
    if (i == 0) g_overflow = 0u;
}

__global__ __launch_bounds__(256, 2)
void cluster_main(const float* __restrict__ x, const float* __restrict__ cc) {
    extern __shared__ char smem[];
    const uint32_t sm = smem_u32(smem);
    const int tid  = threadIdx.x;
    const int wid  = tid >> 5;
    const int lane = tid & 31;

    const int strip = wid >> 1;              // 0..3 : 16-token strip
    const int tb    = strip * 16;
    const int cb    = (wid & 1) * 32;
    const int rbase = tb + (wid & 1) * 8;    // 8 rows this warp loads/converts
    const int barid = strip + 1;

    float2* x2s = (float2*)(smem + SM_X2E);
    unsigned* kcm = (unsigned*)(smem + SM_KC);
    if (tid == 0) *kcm = 0u;

    const float4* xg4 = (const float4*)x;

    int ntiles = 0;
    for (int t = blockIdx.x; t < NUM_TILES; t += GRID_MAIN) ++ntiles;

    auto issue_rows = [&](int tile_idx, int buf) {
        const int tokBase = tile_idx * TILE_TOK;
        const uint32_t base = sm + SM_RAW + (uint32_t)buf * 32768;
        #pragma unroll
        for (int i = 0; i < 8; ++i) {
            int tl = rbase + i;
            int gtok = tokBase + tl;
            if (gtok >= N_TOKENS) gtok = N_TOKENS - 1;
            uint32_t dst = base + (uint32_t)tl * 512 + raw_phys(tl, lane);
            cp_async16(dst, xg4 + (size_t)gtok * 32 + lane);
        }
    };

    int tile = blockIdx.x;
    if (ntiles > 0) issue_rows(tile, 0);
    CP_COMMIT();
    __syncthreads();                         // kcm zero visible

    // ---- centers: convert hi tile + |c|^2 max (all 256 threads; row=tid>>2, q=tid&3) ----
    {
        int rr = tid >> 2, q = tid & 3;
        const float* cg = cc + rr * NFEAT + q * 32;
        float c2h = 0.f;
        #pragma unroll
        for (int c = 0; c < 4; ++c) {
            __half hv[8];
            #pragma unroll
            for (int t = 0; t < 8; ++t) {
                float v = cg[c * 8 + t];
                c2h = fmaf(v, v, c2h);
                hv[t] = __float2half_rn(v);
            }
            uint4 vh;
            vh.x = pack_h2(hv[0], hv[1]); vh.y = pack_h2(hv[2], hv[3]);
            vh.z = pack_h2(hv[4], hv[5]); vh.w = pack_h2(hv[6], hv[7]);
            uint32_t phys = (uint32_t)rr * 256
                          + (uint32_t)(((q * 4 + c) ^ (rr & 7)) * 16);
            *(uint4*)(smem + SM_CHI + phys) = vh;
        }
        float c2 = c2h + __shfl_xor_sync(0xffffffffu, c2h, 1);
        c2 += __shfl_xor_sync(0xffffffffu, c2, 2);
        if (q == 0) atomicMax(kcm, __float_as_uint(c2));
    }
    __syncthreads();
    const float kconst = 1.25f * 0.001953125f * sqrtf(__uint_as_float(*kcm));

    // ---- ldmatrix lane addressing ----
    const int rowA  = tb + (lane & 15);
    const int khA   = lane >> 4;
    const int nrowB = cb + (lane & 7) + ((lane >> 4) & 1) * 8;
    const int khB   = (lane >> 3) & 1;

    int clj[8];
    #pragma unroll
    for (int j = 0; j < 8; ++j)
        clj[j] = cb + (j >> 1) * 8 + 2 * (lane & 3) + (j & 1);

    float rminU[8];
    #pragma unroll
    for (int j = 0; j < 8; ++j) rminU[j] = __int_as_float(0x7f800000);

    const uint32_t slot = (uint32_t)blockIdx.x * 256 + tid;
    unsigned long long* cbuf = g_cand + (size_t)slot * CAP;
    unsigned cnt = 0;

    const int crow = rbase + (lane >> 2);    // row this lane converts
    const int cq   = lane & 3;               // feature quarter

    for (int it = 0; it < ntiles; ++it, tile += GRID_MAIN) {
        const int tokBase = tile * TILE_TOK;
        const int buf = it & 1;

        if (it + 1 < ntiles) issue_rows(tile + GRID_MAIN, buf ^ 1);
        CP_COMMIT();
        CP_WAIT1();

        // ---- convert own rows -> XHI; fused x^2 + E ----
        {
            const char* raw = smem + SM_RAW + (size_t)buf * 32768 + (size_t)crow * 512;
            float ss = 0.f;
            #pragma unroll
            for (int c = 0; c < 4; ++c) {
                float e[8];
                int d0 = cq * 8 + 2 * c;
                *(float4*)(e)     = *(const float4*)(raw + raw_phys(crow, d0));
                *(float4*)(e + 4) = *(const float4*)(raw + raw_phys(crow, d0 + 1));
                __half hv[8];
                #pragma unroll
                for (int t = 0; t < 8; ++t) {
                    float v = e[t];
                    ss = fmaf(v, v, ss);
                    hv[t] = __float2half_rn(v);
                }
                uint4 vh;
                vh.x = pack_h2(hv[0], hv[1]); vh.y = pack_h2(hv[2], hv[3]);
                vh.z = pack_h2(hv[4], hv[5]); vh.w = pack_h2(hv[6], hv[7]);
                uint32_t phys = (uint32_t)crow * 256
                              + (uint32_t)(((cq * 4 + c) ^ (crow & 7)) * 16);
                *(uint4*)(smem + SM_XHI + phys) = vh;
            }
            float tot = ss + __shfl_xor_sync(0xffffffffu, ss, 1);
            tot += __shfl_xor_sync(0xffffffffu, tot, 2);
            if (cq == 0)
                x2s[crow] = make_float2(tot, fmaf(kconst, sqrtf(tot), 1e-4f));
        }
        BAR_PAIR(barid);

        // ---- single-term hi*hi MMA: 8 k-steps, m16 x n32 ----
        float d[4][4];
        #pragma unroll
        for (int nt = 0; nt < 4; ++nt)
            #pragma unroll
            for (int i = 0; i < 4; ++i) d[nt][i] = 0.f;

        const uint32_t abase = sm + SM_XHI;
        const uint32_t bbase = sm + SM_CHI;
        #pragma unroll
        for (int k = 0; k < 8; ++k) {
            uint32_t aF[4], bF[2][4];
            const int ca  = 2 * k + khA;
            const int cbk = 2 * k + khB;
            ldsm4(aF, abase + (uint32_t)(rowA * 256 + ((ca ^ (rowA & 7)) * 16)));
            #pragma unroll
            for (int np = 0; np < 2; ++np) {
                int r = nrowB + np * 16;
                ldsm4(bF[np], bbase + (uint32_t)(r * 256 + ((cbk ^ (r & 7)) * 16)));
            }
            mma16816(d[0], aF, bF[0][0], bF[0][1]);
            mma16816(d[1], aF, bF[0][2], bF[0][3]);
            mma16816(d[2], aF, bF[1][0], bF[1][1]);
            mma16816(d[3], aF, bF[1][2], bF[1][3]);
        }

        // ---- epilogue: interval candidate collection ----
        #pragma unroll
        for (int h = 0; h < 2; ++h) {
            const int tloc = tb + (lane >> 2) + h * 8;
            const int gtok = tokBase + tloc;
            if (gtok < N_TOKENS) {
                const float2 xe = x2s[tloc];
                #pragma unroll
                for (int nt = 0; nt < 4; ++nt) {
                    #pragma unroll
                    for (int p = 0; p < 2; ++p) {
                        const int j = nt * 2 + p;
                        float s = fmaf(-2.f, d[nt][h * 2 + p], xe.x);
                        float U = s + xe.y;
                        float L = s - xe.y;
                        if (U < rminU[j]) rminU[j] = U;
                        if (L <= rminU[j]) {
                            if (cnt < CAP)
                                cbuf[cnt] = ((unsigned long long)fmap(L) << 32)
                                          | ((unsigned long long)clj[j] << 20)
                                          | (unsigned)gtok;
                            ++cnt;
                        }
                    }
                }
            }
        }
        BAR_PAIR(barid);
    }

    g_cnt[slot] = (cnt > CAP) ? CAP : cnt;
    if (cnt > CAP) atomicOr(&g_overflow, 1u);

    #pragma unroll
    for (int j = 0; j < 8; ++j) {
        float v = rminU[j];
        #pragma unroll
        for (int off = 4; off < 32; off <<= 1)
            v = fminf(v, __shfl_xor_sync(0xffffffffu, v, off));
        if ((lane >> 2) == 0) {
            unsigned long long key = ~(((unsigned long long)fmap(v) << 32));
            atomicMax(&g_best[clj[j] * GB_STRIDE], key);
        }
    }
}

// pass 2a: filter candidates against global min-U, bucket by cluster
__global__ void filter_kernel() {
    const uint32_t slot = (uint32_t)blockIdx.x * 256 + threadIdx.x;
    const unsigned n = g_cnt[slot];
    const unsigned long long* cbuf = g_cand + (size_t)slot * CAP;
    for (unsigned i = 0; i < n; ++i) {
        unsigned long long e = cbuf[i];
        unsigned mapL = (unsigned)(e >> 32);
        unsigned cl   = (unsigned)(e >> 20) & 63u;
        unsigned tok  = (unsigned)(e & 0xFFFFFu);
        unsigned gU   = (unsigned)((~g_best[cl * GB_STRIDE]) >> 32);
        if (mapL <= gU) {
            unsigned pos = atomicAdd(&g_shortcnt[cl], 1u);
            if (pos < SCAP) g_short[cl * SCAP + pos] = tok;
            else atomicOr(&g_overflow, 1u);
        }
    }
}

// pass 2b: warp-parallel exact (double) rescore, emit winner row
__global__ void gather_rescore(const float* __restrict__ x,
                               const float* __restrict__ cc,
                               float* __restrict__ out) {
    __shared__ float ck[NFEAT];
    __shared__ double wbd[8];
    __shared__ unsigned wbt[8];
    __shared__ unsigned wtok_s;
    const int k = blockIdx.x;
    const int tid = threadIdx.x;
    const int wid = tid >> 5;
    const int lane = tid & 31;
    if (tid < NFEAT) ck[tid] = cc[k * NFEAT + tid];
    __syncthreads();

    double bd = 1.0e300;
    unsigned bt = 0xFFFFFFFFu;
    const unsigned ovf = g_overflow;
    unsigned n = g_shortcnt[k];
    if (n > SCAP) n = SCAP;

    if (ovf || n == 0) {
        for (unsigned t = tid; t < N_TOKENS; t += 256) {
            double acc = 0.0;
            const float* xr = x + (size_t)t * NFEAT;
            for (int d = 0; d < NFEAT; ++d) {
                double df = (double)xr[d] - (double)ck[d];
                acc += df * df;
            }
            if (acc < bd || (acc == bd && t < bt)) { bd = acc; bt = t; }
        }
        // reduce within warp
        #pragma unroll
        for (int off = 16; off > 0; off >>= 1) {
            double od = __shfl_down_sync(0xffffffffu, bd, off);
            unsigned ot = __shfl_down_sync(0xffffffffu, bt, off);
            if (od < bd || (od == bd && ot < bt)) { bd = od; bt = ot; }
        }
    } else {
        for (unsigned i = wid; i < n; i += 8) {
            unsigned t = g_short[k * SCAP + i];
            const float4* xr = (const float4*)(x + (size_t)t * NFEAT);
            float4 v = xr[lane];
            const float* c4 = ck + lane * 4;
            double acc = 0.0;
            double d0 = (double)v.x - (double)c4[0]; acc += d0 * d0;
            double d1 = (double)v.y - (double)c4[1]; acc += d1 * d1;
            double d2 = (double)v.z - (double)c4[2]; acc += d2 * d2;
            double d3 = (double)v.w - (double)c4[3]; acc += d3 * d3;
            #pragma unroll
            for (int off = 16; off > 0; off >>= 1)
                acc += __shfl_down_sync(0xffffffffu, acc, off);
            acc = __shfl_sync(0xffffffffu, acc, 0);
            if (acc < bd || (acc == bd && t < bt)) { bd = acc; bt = t; }
        }
    }

    if (lane == 0) { wbd[wid] = bd; wbt[wid] = bt; }
    __syncthreads();
    if (tid == 0) {
        double fb = wbd[0]; unsigned ft = wbt[0];
        #pragma unroll
        for (int w = 1; w < 8; ++w) {
            if (wbd[w] < fb || (wbd[w] == fb && wbt[w] < ft)) { fb = wbd[w]; ft = wbt[w]; }
        }
        wtok_s = ft;
    }
    __syncthreads();
    unsigned w = wtok_s;
    if (tid < NFEAT) out[k * NFEAT + tid] = x[(size_t)w * NFEAT + tid];
}

extern "C" void kernel_launch(void* const* d_in, const int* in_sizes, int n_in,
                              void* d_out, int out_size) {
    const float* x;
    const float* cc;
    if (n_in >= 2 && in_sizes[0] == NCLUST * NFEAT) {
        cc = (const float*)d_in[0];
        x  = (const float*)d_in[1];
    } else {
        x  = (const float*)d_in[0];
        cc = (const float*)d_in[1];
    }
    float* out = (float*)d_out;

    cudaFuncSetAttribute(cluster_main,
                         cudaFuncAttributeMaxDynamicSharedMemorySize, SM_TOTAL);

    reset_kernel<<<1, 64>>>();
    cluster_main<<<GRID_MAIN, 256, SM_TOTAL>>>(x, cc);
    filter_kernel<<<GRID_MAIN, 256>>>();
    gather_rescore<<<NCLUST, 256>>>(x, cc, out);
}